// round 5
// baseline (speedup 1.0000x reference)
#include <cuda_runtime.h>

typedef unsigned long long ull;

#define NN 20000
#define EE 100000
#define FNF 92
#define FEF 50
#define DD 64
#define GG 128
#define LL 3
#define YW 4160   // 64*64 + 64 bias cols

// ---------------- device scratch (static; no runtime allocation) ----------------
__device__ float  g_h[NN * DD];
__device__ float  g_hid[(size_t)EE * DD];
__device__ float  g_agg[NN * DD];
__device__ float  g_m[NN * DD];
__device__ float  g_cnt[NN];
__device__ double g_bnsum[DD];
__device__ double g_bnsq[DD];
__device__ float  g_mu[DD];
__device__ float  g_rstd[DD];
__device__ float  g_pool[GG * DD];
__device__ float  g_pcnt[GG];
__device__ float  g_Y[(size_t)NN * YW];
__device__ float  g_w2t[64 * YW];
__device__ float  g_wihT[DD * 192];   // [d][gate*64 + out]
__device__ float  g_whhT[DD * 192];
__device__ int    g_deg[NN];
__device__ int    g_off[NN];
__device__ int    g_rank[EE];
__device__ int    g_eorder[EE];

// ---------------- f32x2 helpers ----------------
__device__ __forceinline__ ull ffma2(ull a, ull b, ull c) {
    ull d; asm("fma.rn.f32x2 %0,%1,%2,%3;" : "=l"(d) : "l"(a), "l"(b), "l"(c));
    return d;
}
__device__ __forceinline__ ull dup2(float x) {
    ull r; asm("mov.b64 %0,{%1,%1};" : "=l"(r) : "f"(x));
    return r;
}

// ---------------- init / CSR build ----------------
__global__ void k_init() {
    int i = blockIdx.x * blockDim.x + threadIdx.x;
    if (i < NN) { g_cnt[i] = 0.f; g_deg[i] = 0; }
    if (i < GG * DD) g_pool[i] = 0.f;
    if (i < GG) g_pcnt[i] = 0.f;
}

__global__ void k_deg(const int* __restrict__ src, const int* __restrict__ dst,
                      const int* __restrict__ batch) {
    int i = blockIdx.x * blockDim.x + threadIdx.x;
    if (i < EE) {
        g_rank[i] = atomicAdd(&g_deg[src[i]], 1);
        atomicAdd(&g_cnt[dst[i]], 1.f);
    }
    if (i < NN) atomicAdd(&g_pcnt[batch[i]], 1.f);
}

__global__ void k_scan() {
    __shared__ int s[1024];
    __shared__ int carry;
    int tid = threadIdx.x;
    if (tid == 0) carry = 0;
    __syncthreads();
    for (int base = 0; base < NN; base += 1024) {
        int v = (base + tid < NN) ? g_deg[base + tid] : 0;
        s[tid] = v;
        __syncthreads();
        for (int off = 1; off < 1024; off <<= 1) {
            int t = (tid >= off) ? s[tid - off] : 0;
            __syncthreads();
            s[tid] += t;
            __syncthreads();
        }
        if (base + tid < NN) g_off[base + tid] = carry + s[tid] - v;
        __syncthreads();
        if (tid == 0) carry += s[1023];
        __syncthreads();
    }
}

__global__ void k_perm(const int* __restrict__ src) {
    int e = blockIdx.x * blockDim.x + threadIdx.x;
    if (e < EE) g_eorder[g_off[src[e]] + g_rank[e]] = e;
}

__global__ void k_zl() {
    int i = blockIdx.x * blockDim.x + threadIdx.x;
    if (i < NN * DD) g_agg[i] = 0.f;
    if (i < DD) { g_bnsum[i] = 0.0; g_bnsq[i] = 0.0; }
}

// ---------------- pre-FC ----------------
__global__ void k_pre(const float* __restrict__ x, const float* __restrict__ w,
                      const float* __restrict__ b) {
    __shared__ float xs[4][FNF];
    int tx = threadIdx.x, ty = threadIdx.y;
    int n = blockIdx.x * 4 + ty;
    for (int f = tx; f < FNF; f += 64) xs[ty][f] = x[(size_t)n * FNF + f];
    __syncthreads();
    float acc = b[tx];
#pragma unroll
    for (int f = 0; f < FNF; ++f) acc += xs[ty][f] * w[f * DD + tx];
    g_h[n * DD + tx] = fmaxf(acc, 0.f);
}

// ---------------- edge MLP stage 1 ----------------
__global__ void k_hid(const float* __restrict__ ea, const float* __restrict__ w,
                      const float* __restrict__ b) {
    __shared__ float es[4][FEF];
    int tx = threadIdx.x, ty = threadIdx.y;
    int e = blockIdx.x * 4 + ty;
    for (int f = tx; f < FEF; f += 64) es[ty][f] = ea[(size_t)e * FEF + f];
    __syncthreads();
    float acc = b[tx];
#pragma unroll
    for (int f = 0; f < FEF; ++f) acc += es[ty][f] * w[f * DD + tx];
    g_hid[(size_t)e * DD + tx] = fmaxf(acc, 0.f);
}

// ---------------- W2 transpose (+ b2 as cols 4096..4159) ----------------
__global__ void k_w2t(const float* __restrict__ W2, const float* __restrict__ b2) {
    int t = blockIdx.x * blockDim.x + threadIdx.x;
    if (t >= 64 * YW) return;
    int i = t / YW, col = t % YW;
    float v;
    if (col < 4096) {
        int j = col >> 6, o = col & 63;
        v = W2[j * 4096 + i * 64 + o];
    } else {
        v = b2[i * 64 + (col - 4096)];
    }
    g_w2t[t] = v;
}

// ---------------- GRU weight transpose: [d][gate*64+out] ----------------
__global__ void k_wtr(const float* __restrict__ wih, const float* __restrict__ whh) {
    int t = blockIdx.x * blockDim.x + threadIdx.x;
    if (t >= DD * 192) return;
    int d = t / 192, k = t % 192;
    g_wihT[t] = wih[k * DD + d];
    g_whhT[t] = whh[k * DD + d];
}

// ---------------- Y GEMM (f32x2 packed): g_Y = g_h @ g_w2t ----------------
// A stored duplicated: hsT2[k][2m]=hsT2[k][2m+1]=h[m,k]; one LDS.128 -> two dup pairs.
// Row pad 136 floats (mult of 4 for LDS.128 alignment; 136%32=8 spreads banks).
__global__ void __launch_bounds__(256) k_ygemm() {
    __shared__ __align__(16) float hsT2[64][136];
    int tid = threadIdx.x;
    int mb = blockIdx.x * 64;
    int nb = blockIdx.y * 256;
    for (int t = tid; t < 1024; t += 256) {
        int m = t >> 4, q = t & 15;
        int gm = mb + m;
        float4 v = make_float4(0.f, 0.f, 0.f, 0.f);
        if (gm < NN) v = *(const float4*)&g_h[gm * DD + q * 4];
        *(ull*)&hsT2[q * 4 + 0][2 * m] = dup2(v.x);
        *(ull*)&hsT2[q * 4 + 1][2 * m] = dup2(v.y);
        *(ull*)&hsT2[q * 4 + 2][2 * m] = dup2(v.z);
        *(ull*)&hsT2[q * 4 + 3][2 * m] = dup2(v.w);
    }
    __syncthreads();
    int mg = tid >> 5, ng = tid & 31;
    int m0 = mg * 8;             // 8 rows per thread
    int n0 = nb + ng * 8;        // 8 cols per thread (4 f32x2 pairs)
    if (n0 >= YW) return;
    ull acc2[8][4];
#pragma unroll
    for (int a = 0; a < 8; a++)
#pragma unroll
        for (int b = 0; b < 4; b++) acc2[a][b] = 0ULL;
    const float* Bp = g_w2t + n0;
#pragma unroll 4
    for (int k = 0; k < 64; k++) {
        ulonglong2 aA = *(const ulonglong2*)&hsT2[k][2 * m0];
        ulonglong2 aB = *(const ulonglong2*)&hsT2[k][2 * m0 + 4];
        ulonglong2 aC = *(const ulonglong2*)&hsT2[k][2 * m0 + 8];
        ulonglong2 aD = *(const ulonglong2*)&hsT2[k][2 * m0 + 12];
        ulonglong2 b0 = *(const ulonglong2*)&Bp[k * YW];
        ulonglong2 b1 = *(const ulonglong2*)&Bp[k * YW + 4];
        ull av[8] = {aA.x, aA.y, aB.x, aB.y, aC.x, aC.y, aD.x, aD.y};
        ull bv[4] = {b0.x, b0.y, b1.x, b1.y};
#pragma unroll
        for (int mm = 0; mm < 8; mm++)
#pragma unroll
            for (int nn = 0; nn < 4; nn++)
                acc2[mm][nn] = ffma2(av[mm], bv[nn], acc2[mm][nn]);
    }
#pragma unroll
    for (int mm = 0; mm < 8; mm++) {
        int gm = mb + m0 + mm;
        if (gm >= NN) continue;
        float* Cp = g_Y + (size_t)gm * YW + n0;
        *(ulonglong2*)Cp       = make_ulonglong2(acc2[mm][0], acc2[mm][1]);
        *(ulonglong2*)(Cp + 4) = make_ulonglong2(acc2[mm][2], acc2[mm][3]);
    }
}

// ---------------- edge phase: msg = hid @ Y[src] + bias; scatter ----------------
__global__ void __launch_bounds__(256) k_edge(const int* __restrict__ src,
                                              const int* __restrict__ dst) {
    __shared__ float hid_s[32][64];
    __shared__ int ssrc[32], sdst[32], seo[32];
    int tid = threadIdx.x;
    int eb0 = blockIdx.x * 32;
    if (tid < 32) {
        int eo = g_eorder[eb0 + tid];
        seo[tid] = eo;
        ssrc[tid] = src[eo];
        sdst[tid] = dst[eo];
    }
    __syncthreads();
    for (int t = tid; t < 32 * 16; t += 256) {
        int el = t >> 4, q = t & 15;
        *(float4*)&hid_s[el][q * 4] = *(const float4*)&g_hid[(size_t)seo[el] * DD + q * 4];
    }
    __syncthreads();
    int o4 = (tid & 15) * 4;
    int el0 = tid >> 4;
#pragma unroll
    for (int m = 0; m < 2; m++) {
        int el = el0 + 16 * m;
        const float* Yr = g_Y + (size_t)ssrc[el] * YW;
        float4 acc = *(const float4*)&Yr[4096 + o4];
#pragma unroll 8
        for (int j = 0; j < 64; j++) {
            float hj = hid_s[el][j];
            float4 yv = *(const float4*)&Yr[j * 64 + o4];
            acc.x += hj * yv.x; acc.y += hj * yv.y;
            acc.z += hj * yv.z; acc.w += hj * yv.w;
        }
        float* ap = g_agg + (size_t)sdst[el] * DD + o4;
        atomicAdd(ap + 0, acc.x); atomicAdd(ap + 1, acc.y);
        atomicAdd(ap + 2, acc.z); atomicAdd(ap + 3, acc.w);
    }
}

// ---------------- conv combine + BN stats ----------------
__global__ void k_bn1(const float* __restrict__ root, const float* __restrict__ cb) {
    __shared__ float hs[4][DD];
    __shared__ float ms[4][DD];
    int tx = threadIdx.x, ty = threadIdx.y;
    int n = blockIdx.x * 4 + ty;
    hs[ty][tx] = g_h[n * DD + tx];
    __syncthreads();
    float c = g_cnt[n];
    float acc = g_agg[n * DD + tx] / fmaxf(c, 1.f) + cb[tx];
#pragma unroll
    for (int d = 0; d < DD; ++d) acc += hs[ty][d] * root[d * DD + tx];
    g_m[n * DD + tx] = acc;
    ms[ty][tx] = acc;
    __syncthreads();
    if (ty == 0) {
        float s  = ms[0][tx] + ms[1][tx] + ms[2][tx] + ms[3][tx];
        float sq = ms[0][tx] * ms[0][tx] + ms[1][tx] * ms[1][tx] +
                   ms[2][tx] * ms[2][tx] + ms[3][tx] * ms[3][tx];
        atomicAdd(&g_bnsum[tx], (double)s);
        atomicAdd(&g_bnsq[tx], (double)sq);
    }
}

__global__ void k_bnfin() {
    int o = threadIdx.x;
    double mu = g_bnsum[o] / (double)NN;
    double var = g_bnsq[o] / (double)NN - mu * mu;
    g_mu[o] = (float)mu;
    g_rstd[o] = rsqrtf((float)var + 1e-5f);
}

// ---------------- BN-apply + relu + GRU, 4 nodes/thread ----------------
// Block (64,4): 16 nodes/block; weights read once per 4 nodes -> LSU /4.
__global__ void __launch_bounds__(256) k_gru(const float* __restrict__ gamma,
                                             const float* __restrict__ beta,
                                             const float* __restrict__ bih,
                                             const float* __restrict__ bhh) {
    __shared__ float ms[16][DD];
    __shared__ float hs[16][DD];
    int tx = threadIdx.x, ty = threadIdx.y;
    int tid = ty * 64 + tx;
    int nb = blockIdx.x * 16;
    for (int t = tid; t < 1024; t += 256) {
        int i = t >> 6, d = t & 63;
        int n = nb + i;
        float mv = g_m[n * DD + d];
        mv = gamma[d] * (mv - g_mu[d]) * g_rstd[d] + beta[d];
        ms[i][d] = fmaxf(mv, 0.f);
        hs[i][d] = g_h[n * DD + d];
    }
    __syncthreads();
    float gr[4], gz[4], gn[4], hr[4], hz[4], hn[4];
    float b0 = bih[tx], b1 = bih[DD + tx], b2 = bih[2 * DD + tx];
    float c0 = bhh[tx], c1 = bhh[DD + tx], c2 = bhh[2 * DD + tx];
#pragma unroll
    for (int r = 0; r < 4; r++) {
        gr[r] = b0; gz[r] = b1; gn[r] = b2;
        hr[r] = c0; hz[r] = c1; hn[r] = c2;
    }
    int i0 = ty * 4;
#pragma unroll 4
    for (int d = 0; d < DD; ++d) {
        const float* wT = g_wihT + d * 192;
        const float* vT = g_whhT + d * 192;
        float w0 = wT[tx], w1 = wT[64 + tx], w2 = wT[128 + tx];
        float v0 = vT[tx], v1 = vT[64 + tx], v2 = vT[128 + tx];
#pragma unroll
        for (int r = 0; r < 4; r++) {
            float md = ms[i0 + r][d], hd = hs[i0 + r][d];
            gr[r] += md * w0; gz[r] += md * w1; gn[r] += md * w2;
            hr[r] += hd * v0; hz[r] += hd * v1; hn[r] += hd * v2;
        }
    }
#pragma unroll
    for (int r = 0; r < 4; r++) {
        int n = nb + i0 + r;
        float hvv = hs[i0 + r][tx];
        float rr = 1.f / (1.f + __expf(-(gr[r] + hr[r])));
        float zz = 1.f / (1.f + __expf(-(gz[r] + hz[r])));
        float nn2 = tanhf(gn[r] + rr * hn[r]);
        g_h[n * DD + tx] = (1.f - zz) * nn2 + zz * hvv;
    }
}

// ---------------- pooling + head ----------------
__global__ void k_pool(const int* __restrict__ batch) {
    int i = blockIdx.x * blockDim.x + threadIdx.x;
    if (i >= NN * DD) return;
    int n = i >> 6, o = i & 63;
    atomicAdd(&g_pool[batch[n] * DD + o], g_h[i]);
}

__global__ void k_head(const float* __restrict__ pw, const float* __restrict__ pb,
                       const float* __restrict__ ow, const float* __restrict__ ob,
                       float* __restrict__ out) {
    __shared__ float p[DD];
    __shared__ float q[DD];
    int g = blockIdx.x, o = threadIdx.x;
    p[o] = g_pool[g * DD + o] / fmaxf(g_pcnt[g], 1.f);
    __syncthreads();
    float acc = pb[o];
#pragma unroll
    for (int d = 0; d < DD; ++d) acc += p[d] * pw[d * DD + o];
    q[o] = fmaxf(acc, 0.f) * ow[o];
    __syncthreads();
    if (o == 0) {
        float s = ob[0];
        for (int d = 0; d < DD; ++d) s += q[d];
        out[g] = s;
    }
}

// ---------------- launch ----------------
extern "C" void kernel_launch(void* const* d_in, const int* in_sizes, int n_in,
                              void* d_out, int out_size) {
    const float* x     = (const float*)d_in[0];
    const int*   ei    = (const int*)d_in[1];
    const float* ea    = (const float*)d_in[2];
    const int*   batch = (const int*)d_in[3];
    const float* pre_w = (const float*)d_in[4];
    const float* pre_b = (const float*)d_in[5];
    const float* ew1   = (const float*)d_in[6];
    const float* eb1   = (const float*)d_in[7];
    const float* ew2   = (const float*)d_in[8];
    const float* eb2   = (const float*)d_in[9];
    const float* root  = (const float*)d_in[10];
    const float* cb    = (const float*)d_in[11];
    const float* bng   = (const float*)d_in[12];
    const float* bnb   = (const float*)d_in[13];
    const float* wih   = (const float*)d_in[14];
    const float* whh   = (const float*)d_in[15];
    const float* bih   = (const float*)d_in[16];
    const float* bhh   = (const float*)d_in[17];
    const float* pw    = (const float*)d_in[18];
    const float* pb    = (const float*)d_in[19];
    const float* ow    = (const float*)d_in[20];
    const float* ob    = (const float*)d_in[21];
    float* out = (float*)d_out;
    const int* src = ei;
    const int* dst = ei + EE;

    k_init<<<(NN + 255) / 256, 256>>>();
    k_deg<<<(EE + 255) / 256, 256>>>(src, dst, batch);
    k_scan<<<1, 1024>>>();
    k_perm<<<(EE + 255) / 256, 256>>>(src);
    k_pre<<<NN / 4, dim3(64, 4)>>>(x, pre_w, pre_b);

    for (int l = 0; l < LL; l++) {
        k_zl<<<(NN * DD + 255) / 256, 256>>>();
        k_hid<<<EE / 4, dim3(64, 4)>>>(ea, ew1 + (size_t)l * FEF * DD, eb1 + l * DD);
        k_w2t<<<(64 * YW + 255) / 256, 256>>>(ew2 + (size_t)l * DD * DD * DD,
                                              eb2 + (size_t)l * DD * DD);
        k_wtr<<<(DD * 192 + 255) / 256, 256>>>(wih + (size_t)l * 3 * DD * DD,
                                               whh + (size_t)l * 3 * DD * DD);
        k_ygemm<<<dim3((NN + 63) / 64, (YW + 255) / 256), 256>>>();
        k_edge<<<EE / 32, 256>>>(src, dst);
        k_bn1<<<NN / 4, dim3(64, 4)>>>(root + (size_t)l * DD * DD, cb + l * DD);
        k_bnfin<<<1, 64>>>();
        k_gru<<<NN / 16, dim3(64, 4)>>>(bng + l * DD, bnb + l * DD,
                                        bih + (size_t)l * 3 * DD,
                                        bhh + (size_t)l * 3 * DD);
    }

    k_pool<<<(NN * DD + 255) / 256, 256>>>(batch);
    k_head<<<GG, 64>>>(pw, pb, ow, ob, out);
}